// round 7
// baseline (speedup 1.0000x reference)
#include <cuda_runtime.h>
#include <math.h>
#include <math_constants.h>

#define THREADS 256
#define NBUCKET 32
#define MAXB 32768          // max batch rows supported by split path (2 MB scratch)

__device__ float g_acc[NBUCKET][64];     // soft at [b][0..15], hard at [b][32..47]
__device__ float g_gp[MAXB * 16];        // per-row normalized permuted gates

__global__ void init_acc_kernel() {
    g_acc[blockIdx.x][threadIdx.x] = 0.f;   // <<<NBUCKET, 64>>>
}

__global__ void finalize_kernel(float* __restrict__ out_tail, float invB, int E) {
    int t = threadIdx.x;
    if (t < 2 * E) {
        int idx = (t < E) ? t : (32 + (t - E));
        float s = 0.f;
        #pragma unroll
        for (int b = 0; b < NBUCKET; b++) s += g_acc[b][idx];
        out_tail[t] = s * invB;
    }
}

// ---------------------------------------------------------------------------
// Kernel 1: gating. E==16. 32 rows per block, 16 threads per row-group.
// gate staged in smem with +1-pad rows -> conflict-free expert-strided reads.
// ---------------------------------------------------------------------------
__global__ __launch_bounds__(THREADS) void gate16_kernel(
    const float* __restrict__ x, const float* __restrict__ perm,
    const float* __restrict__ gate, const float* __restrict__ bias,
    int B, int DIN, int P)
{
    constexpr int E = 16;
    __shared__ float gs[E * 513];      // padded gate rows
    __shared__ float pw[E * E];
    __shared__ float lrow[16][16];     // per-group logits
    __shared__ float grow[16][16];     // per-group normalized gates

    const int tid = threadIdx.x;

    for (int i = tid; i < E * DIN; i += THREADS) {
        int e = i / DIN, k = i - e * DIN;
        gs[e * 513 + k] = gate[i];
    }
    const float invP = 1.f / (float)P;
    for (int i = tid; i < E * E; i += THREADS) {
        float s = 0.f;
        for (int p = 0; p < P; p++) s += perm[p * E * E + i];
        pw[i] = s * invP;
    }
    __syncthreads();

    const int g = tid >> 4;        // group 0..15 (row within half-tile)
    const int j = tid & 15;        // expert index
    const float* gr = gs + j * 513;

    for (int rr = 0; rr < 2; rr++) {
        const int b = blockIdx.x * 32 + rr * 16 + g;
        if (b < B) {
            const float* xr = x + (size_t)b * DIN;
            float s = 0.f;
            #pragma unroll 4
            for (int k = 0; k < DIN; k++) s += __ldg(xr + k) * gr[k];
            lrow[g][j] = s + bias[j];
        }
        __syncwarp();
        if (b < B && j == 0) {
            float v1 = -CUDART_INF_F; int i1 = 0;
            #pragma unroll
            for (int i = 0; i < E; i++) if (lrow[g][i] > v1) { v1 = lrow[g][i]; i1 = i; }
            float v2 = -CUDART_INF_F; int i2 = 0;
            #pragma unroll
            for (int i = 0; i < E; i++) if (i != i1 && lrow[g][i] > v2) { v2 = lrow[g][i]; i2 = i; }
            // faithful tf.where(scattered == 0 -> -inf)
            float m1 = (v1 == 0.f) ? -CUDART_INF_F : v1;
            float m2 = (v2 == 0.f) ? -CUDART_INF_F : v2;
            float m  = fmaxf(m1, m2);
            float e1 = __expf(m1 - m), e2 = __expf(m2 - m);
            float zi = 1.f / (e1 + e2);
            float g1 = e1 * zi, g2 = e2 * zi;
            float raw[E]; float s = 0.f;
            #pragma unroll
            for (int q = 0; q < E; q++) {
                raw[q] = g1 * pw[i1 * E + q] + g2 * pw[i2 * E + q];
                s += raw[q];
            }
            const float rinv = 1.f / s;
            #pragma unroll
            for (int q = 0; q < E; q++) grow[g][q] = raw[q] * rinv;
        }
        __syncwarp();
        if (b < B) {
            const float v = grow[g][j];
            g_gp[(size_t)b * E + j] = v;
            const int bucket = b & (NBUCKET - 1);
            atomicAdd(&g_acc[bucket][j], v);
            atomicAdd(&g_acc[bucket][32 + j], (v < 1e-5f) ? 0.f : 1.f);
        }
        __syncwarp();
    }
}

// ---------------------------------------------------------------------------
// Kernel 2: pure streaming pass. One block per row b, zero prologue.
// ---------------------------------------------------------------------------
__global__ __launch_bounds__(THREADS) void stream16_kernel(
    const float* __restrict__ f, float* __restrict__ y, int D)
{
    constexpr int E = 16;
    const int b = blockIdx.x;
    const float4* w4 = (const float4*)(g_gp + (size_t)b * E);
    const float4 w0 = __ldg(w4 + 0);
    const float4 w1 = __ldg(w4 + 1);
    const float4 w2 = __ldg(w4 + 2);
    const float4 w3 = __ldg(w4 + 3);

    const size_t base = (size_t)b * D * E;
    float* yr = y + (size_t)b * D;
    for (int d = threadIdx.x; d < D; d += THREADS) {
        const float4* fr = (const float4*)(f + base + (size_t)d * E);
        float4 a0 = __ldg(fr + 0), a1 = __ldg(fr + 1);
        float4 a2 = __ldg(fr + 2), a3 = __ldg(fr + 3);
        float acc = a0.x * w0.x + a0.y * w0.y + a0.z * w0.z + a0.w * w0.w
                  + a1.x * w1.x + a1.y * w1.y + a1.z * w1.z + a1.w * w1.w
                  + a2.x * w2.x + a2.y * w2.y + a2.z * w2.z + a2.w * w2.w
                  + a3.x * w3.x + a3.y * w3.y + a3.z * w3.z + a3.w * w3.w;
        yr[d] = acc;
    }
}

// ---------------------------------------------------------------------------
// Generic fallback (any E <= 32)
// ---------------------------------------------------------------------------
__global__ void fused_generic_kernel(
    const float* __restrict__ f, const float* __restrict__ x,
    const float* __restrict__ perm, const float* __restrict__ gate,
    const float* __restrict__ bias, float* __restrict__ y,
    int D, int DIN, int P, int E)
{
    extern __shared__ float smem[];
    float* xs     = smem;
    float* pw     = xs + DIN;
    float* logits = pw + E * E;
    float* gp     = logits + E;
    const int tid = threadIdx.x;
    const int b   = blockIdx.x;

    for (int k = tid; k < DIN; k += blockDim.x) xs[k] = x[(size_t)b * DIN + k];
    const float invP = 1.f / (float)P;
    for (int i = tid; i < E * E; i += blockDim.x) {
        float s = 0.f;
        for (int p = 0; p < P; p++) s += perm[p * E * E + i];
        pw[i] = s * invP;
    }
    __syncthreads();
    for (int e = tid; e < E; e += blockDim.x) {
        float s = 0.f;
        const float* gr = gate + (size_t)e * DIN;
        for (int k = 0; k < DIN; k++) s += xs[k] * gr[k];
        logits[e] = s + bias[e];
    }
    __syncthreads();
    if (tid == 0) {
        float v1 = -CUDART_INF_F; int i1 = 0;
        for (int i = 0; i < E; i++) if (logits[i] > v1) { v1 = logits[i]; i1 = i; }
        float v2 = -CUDART_INF_F; int i2 = 0;
        for (int i = 0; i < E; i++) if (i != i1 && logits[i] > v2) { v2 = logits[i]; i2 = i; }
        float m1 = (v1 == 0.f) ? -CUDART_INF_F : v1;
        float m2 = (v2 == 0.f) ? -CUDART_INF_F : v2;
        float m  = fmaxf(m1, m2);
        float e1 = __expf(m1 - m), e2 = __expf(m2 - m);
        float zi = 1.f / (e1 + e2);
        float g1 = e1 * zi, g2 = e2 * zi;
        float s = 0.f;
        for (int q = 0; q < E; q++) {
            float r = g1 * pw[i1 * E + q] + g2 * pw[i2 * E + q];
            gp[q] = r; s += r;
        }
        const float rinv = 1.f / s;
        const int bucket = b & (NBUCKET - 1);
        for (int q = 0; q < E; q++) {
            float v = gp[q] * rinv;
            gp[q] = v;
            if (q < 32) {
                atomicAdd(&g_acc[bucket][q], v);
                atomicAdd(&g_acc[bucket][32 + q], (v < 1e-5f) ? 0.f : 1.f);
            }
        }
    }
    __syncthreads();
    const size_t base = (size_t)b * D * E;
    for (int d = tid; d < D; d += blockDim.x) {
        const float* fr = f + base + (size_t)d * E;
        float acc = 0.f;
        for (int e = 0; e < E; e++) acc += fr[e] * gp[e];
        y[(size_t)b * D + d] = acc;
    }
}

extern "C" void kernel_launch(void* const* d_in, const int* in_sizes, int n_in,
                              void* d_out, int out_size) {
    const float* f    = (const float*)d_in[0];
    const float* x    = (const float*)d_in[1];
    const float* perm = (const float*)d_in[2];
    const float* gate = (const float*)d_in[3];
    const float* bias = (const float*)d_in[4];

    const int E   = in_sizes[4];
    const int DIN = in_sizes[3] / E;
    const int B   = in_sizes[1] / DIN;
    const int D   = (int)((long long)in_sizes[0] / ((long long)B * E));
    const int P   = in_sizes[2] / (E * E);
    float* y = (float*)d_out;

    init_acc_kernel<<<NBUCKET, 64>>>();

    if (E == 16 && E * DIN <= 16 * 512 && D % 16 == 0 && B <= MAXB) {
        gate16_kernel<<<(B + 31) / 32, THREADS>>>(x, perm, gate, bias, B, DIN, P);
        stream16_kernel<<<B, THREADS>>>(f, y, D);
    } else {
        const size_t smem = (size_t)(DIN + E * E + 2 * E + 8) * sizeof(float);
        fused_generic_kernel<<<B, THREADS, smem>>>(f, x, perm, gate, bias, y, D, DIN, P, E);
    }

    const long long tail = (long long)B * D;
    if ((long long)out_size >= tail + 2LL * E)
        finalize_kernel<<<1, ((2 * E + 31) / 32) * 32>>>(y + tail, 1.f / (float)B, E);
}

// round 9
// speedup vs baseline: 1.0296x; 1.0296x over previous
#include <cuda_runtime.h>
#include <math.h>
#include <math_constants.h>

#define THREADS 256
#define NBUCKET 32
#define MAXB 32768
#define GATE_BLOCKS 128

__device__ float g_acc[NBUCKET][64];     // soft at [b][0..15], hard at [b][32..47]
__device__ float g_gp[MAXB * 16];        // per-row normalized permuted gates

__global__ void init_acc_kernel() {
    g_acc[blockIdx.x][threadIdx.x] = 0.f;   // <<<NBUCKET, 64>>>
}

__global__ void finalize_kernel(float* __restrict__ out_tail, float invB, int E) {
    int t = threadIdx.x;
    if (t < 2 * E) {
        int idx = (t < E) ? t : (32 + (t - E));
        float s = 0.f;
        #pragma unroll
        for (int b = 0; b < NBUCKET; b++) s += g_acc[b][idx];
        out_tail[t] = s * invB;
    }
}

// ---------------------------------------------------------------------------
// Gating: warp per row. Coalesced x loads, 16 register accumulators,
// XOR-butterfly reduce -> every lane holds all logits -> redundant epilogue.
// Requires E==16, DIN % 32 == 0, DIN <= 512.
// ---------------------------------------------------------------------------
__global__ __launch_bounds__(THREADS) void gate16_kernel(
    const float* __restrict__ x, const float* __restrict__ perm,
    const float* __restrict__ gate, const float* __restrict__ bias,
    int B, int DIN, int P)
{
    constexpr int E = 16;
    __shared__ float gs[E * 513];      // padded gate rows: bank = (e + k) & 31
    __shared__ float pw[E * E];
    __shared__ float bs[E];

    const int tid  = threadIdx.x;
    const int lane = tid & 31;
    const int nK   = DIN >> 5;         // k-iterations per lane

    for (int i = tid; i < E * DIN; i += THREADS) {
        int e = i / DIN, k = i - e * DIN;
        gs[e * 513 + k] = gate[i];
    }
    const float invP = 1.f / (float)P;
    for (int i = tid; i < E * E; i += THREADS) {
        float s = 0.f;
        for (int p = 0; p < P; p++) s += perm[p * E * E + i];
        pw[i] = s * invP;
    }
    if (tid < E) bs[tid] = bias[tid];
    __syncthreads();

    const int warpsTotal = GATE_BLOCKS * (THREADS / 32);
    const int w = blockIdx.x * (THREADS / 32) + (tid >> 5);

    for (int b = w; b < B; b += warpsTotal) {
        const float* xr = x + (size_t)b * DIN;
        float acc[E];
        #pragma unroll
        for (int e = 0; e < E; e++) acc[e] = 0.f;

        for (int i = 0; i < nK; i++) {
            const int k = lane + (i << 5);
            const float xv = xr[k];                       // coalesced 128B
            const float* gcol = gs + k;                   // gs[e*513 + k]
            #pragma unroll
            for (int e = 0; e < E; e++) acc[e] += xv * gcol[e * 513];
        }
        // butterfly: every lane gets full sums
        #pragma unroll
        for (int off = 16; off > 0; off >>= 1) {
            #pragma unroll
            for (int e = 0; e < E; e++)
                acc[e] += __shfl_xor_sync(0xffffffffu, acc[e], off);
        }
        #pragma unroll
        for (int e = 0; e < E; e++) acc[e] += bs[e];

        // top-2 -> faithful (==0 -> -inf) softmax -> permute -> normalize
        float v1 = -CUDART_INF_F; int i1 = 0;
        #pragma unroll
        for (int i = 0; i < E; i++) if (acc[i] > v1) { v1 = acc[i]; i1 = i; }
        float v2 = -CUDART_INF_F; int i2 = 0;
        #pragma unroll
        for (int i = 0; i < E; i++) if (i != i1 && acc[i] > v2) { v2 = acc[i]; i2 = i; }
        float m1 = (v1 == 0.f) ? -CUDART_INF_F : v1;
        float m2 = (v2 == 0.f) ? -CUDART_INF_F : v2;
        float m  = fmaxf(m1, m2);
        float e1 = __expf(m1 - m), e2 = __expf(m2 - m);
        float zi = 1.f / (e1 + e2);
        float g1 = e1 * zi, g2 = e2 * zi;
        float s = 0.f;
        float raw[E];
        #pragma unroll
        for (int q = 0; q < E; q++) {
            raw[q] = g1 * pw[i1 * E + q] + g2 * pw[i2 * E + q];
            s += raw[q];
        }
        const float rinv = 1.f / s;

        const int bucket = b & (NBUCKET - 1);
        if (lane < E) {
            const float v = raw[lane] * rinv;
            g_gp[(size_t)b * E + lane] = v;               // coalesced 64B
            atomicAdd(&g_acc[bucket][lane], v);
        } else {
            const float v = raw[lane - E] * rinv;
            atomicAdd(&g_acc[bucket][32 + (lane - E)], (v < 1e-5f) ? 0.f : 1.f);
        }
    }
}

// ---------------------------------------------------------------------------
// Streaming pass: one block per row, zero prologue, front-batched LDG.128.
// ---------------------------------------------------------------------------
__global__ __launch_bounds__(THREADS) void stream16_kernel(
    const float* __restrict__ f, float* __restrict__ y, int D)
{
    constexpr int E = 16;
    const int b = blockIdx.x;
    const float4* w4 = (const float4*)(g_gp + (size_t)b * E);
    const float4 w0 = w4[0], w1 = w4[1], w2 = w4[2], w3 = w4[3];

    const float4* fb = (const float4*)(f + (size_t)b * D * E);
    float* yr = y + (size_t)b * D;

    if (D == 2 * THREADS) {
        const int d0 = threadIdx.x, d1 = threadIdx.x + THREADS;
        const float4* p0 = fb + (size_t)d0 * 4;
        const float4* p1 = fb + (size_t)d1 * 4;
        float4 a0 = p0[0], a1 = p0[1], a2 = p0[2], a3 = p0[3];
        float4 c0 = p1[0], c1 = p1[1], c2 = p1[2], c3 = p1[3];
        float r0 = a0.x*w0.x + a0.y*w0.y + a0.z*w0.z + a0.w*w0.w
                 + a1.x*w1.x + a1.y*w1.y + a1.z*w1.z + a1.w*w1.w
                 + a2.x*w2.x + a2.y*w2.y + a2.z*w2.z + a2.w*w2.w
                 + a3.x*w3.x + a3.y*w3.y + a3.z*w3.z + a3.w*w3.w;
        float r1 = c0.x*w0.x + c0.y*w0.y + c0.z*w0.z + c0.w*w0.w
                 + c1.x*w1.x + c1.y*w1.y + c1.z*w1.z + c1.w*w1.w
                 + c2.x*w2.x + c2.y*w2.y + c2.z*w2.z + c2.w*w2.w
                 + c3.x*w3.x + c3.y*w3.y + c3.z*w3.z + c3.w*w3.w;
        yr[d0] = r0;
        yr[d1] = r1;
    } else {
        for (int d = threadIdx.x; d < D; d += THREADS) {
            const float4* fr = fb + (size_t)d * 4;
            float4 a0 = fr[0], a1 = fr[1], a2 = fr[2], a3 = fr[3];
            float acc = a0.x*w0.x + a0.y*w0.y + a0.z*w0.z + a0.w*w0.w
                      + a1.x*w1.x + a1.y*w1.y + a1.z*w1.z + a1.w*w1.w
                      + a2.x*w2.x + a2.y*w2.y + a2.z*w2.z + a2.w*w2.w
                      + a3.x*w3.x + a3.y*w3.y + a3.z*w3.z + a3.w*w3.w;
            yr[d] = acc;
        }
    }
}

// ---------------------------------------------------------------------------
// Generic fallback (any E <= 32)
// ---------------------------------------------------------------------------
__global__ void fused_generic_kernel(
    const float* __restrict__ f, const float* __restrict__ x,
    const float* __restrict__ perm, const float* __restrict__ gate,
    const float* __restrict__ bias, float* __restrict__ y,
    int D, int DIN, int P, int E)
{
    extern __shared__ float smem[];
    float* xs     = smem;
    float* pw     = xs + DIN;
    float* logits = pw + E * E;
    float* gp     = logits + E;
    const int tid = threadIdx.x;
    const int b   = blockIdx.x;

    for (int k = tid; k < DIN; k += blockDim.x) xs[k] = x[(size_t)b * DIN + k];
    const float invP = 1.f / (float)P;
    for (int i = tid; i < E * E; i += blockDim.x) {
        float s = 0.f;
        for (int p = 0; p < P; p++) s += perm[p * E * E + i];
        pw[i] = s * invP;
    }
    __syncthreads();
    for (int e = tid; e < E; e += blockDim.x) {
        float s = 0.f;
        const float* gr = gate + (size_t)e * DIN;
        for (int k = 0; k < DIN; k++) s += xs[k] * gr[k];
        logits[e] = s + bias[e];
    }
    __syncthreads();
    if (tid == 0) {
        float v1 = -CUDART_INF_F; int i1 = 0;
        for (int i = 0; i < E; i++) if (logits[i] > v1) { v1 = logits[i]; i1 = i; }
        float v2 = -CUDART_INF_F; int i2 = 0;
        for (int i = 0; i < E; i++) if (i != i1 && logits[i] > v2) { v2 = logits[i]; i2 = i; }
        float m1 = (v1 == 0.f) ? -CUDART_INF_F : v1;
        float m2 = (v2 == 0.f) ? -CUDART_INF_F : v2;
        float m  = fmaxf(m1, m2);
        float e1 = __expf(m1 - m), e2 = __expf(m2 - m);
        float zi = 1.f / (e1 + e2);
        float g1 = e1 * zi, g2 = e2 * zi;
        float s = 0.f;
        for (int q = 0; q < E; q++) {
            float r = g1 * pw[i1 * E + q] + g2 * pw[i2 * E + q];
            gp[q] = r; s += r;
        }
        const float rinv = 1.f / s;
        const int bucket = b & (NBUCKET - 1);
        for (int q = 0; q < E; q++) {
            float v = gp[q] * rinv;
            gp[q] = v;
            if (q < 32) {
                atomicAdd(&g_acc[bucket][q], v);
                atomicAdd(&g_acc[bucket][32 + q], (v < 1e-5f) ? 0.f : 1.f);
            }
        }
    }
    __syncthreads();
    const size_t base = (size_t)b * D * E;
    for (int d = tid; d < D; d += blockDim.x) {
        const float* fr = f + base + (size_t)d * E;
        float acc = 0.f;
        for (int e = 0; e < E; e++) acc += fr[e] * gp[e];
        y[(size_t)b * D + d] = acc;
    }
}

extern "C" void kernel_launch(void* const* d_in, const int* in_sizes, int n_in,
                              void* d_out, int out_size) {
    const float* f    = (const float*)d_in[0];
    const float* x    = (const float*)d_in[1];
    const float* perm = (const float*)d_in[2];
    const float* gate = (const float*)d_in[3];
    const float* bias = (const float*)d_in[4];

    const int E   = in_sizes[4];
    const int DIN = in_sizes[3] / E;
    const int B   = in_sizes[1] / DIN;
    const int D   = (int)((long long)in_sizes[0] / ((long long)B * E));
    const int P   = in_sizes[2] / (E * E);
    float* y = (float*)d_out;

    init_acc_kernel<<<NBUCKET, 64>>>();

    if (E == 16 && DIN % 32 == 0 && DIN <= 512 && D % 16 == 0 && B <= MAXB) {
        gate16_kernel<<<GATE_BLOCKS, THREADS>>>(x, perm, gate, bias, B, DIN, P);
        stream16_kernel<<<B, THREADS>>>(f, y, D);
    } else {
        const size_t smem = (size_t)(DIN + E * E + 2 * E + 8) * sizeof(float);
        fused_generic_kernel<<<B, THREADS, smem>>>(f, x, perm, gate, bias, y, D, DIN, P, E);
    }

    const long long tail = (long long)B * D;
    if ((long long)out_size >= tail + 2LL * E)
        finalize_kernel<<<1, ((2 * E + 31) / 32) * 32>>>(y + tail, 1.f / (float)B, E);
}